// round 2
// baseline (speedup 1.0000x reference)
#include <cuda_runtime.h>

// Burden_29145648070955: strategic-training forward path, reduced to
//   s_{t+1} = (X.w + b) + 0.5*||w||^2 * nab(s_t),  output = s_21.
// One streaming matvec over X + per-row scalar recurrence. HBM-bound.
//
// R2: single-row software pipeline (A/B register double buffer) so each warp
// keeps loads in flight during the dependent dot/shuffle window, plus a
// 6-shuffle merged two-row reduction (was 10).

#define BATCH   65536
#define DIM     1024
#define THREADS 128
#define WARPS   (THREADS / 32)
#define ROWS_PER_WARP  32
#define ROWS_PER_BLOCK (WARPS * ROWS_PER_WARP)   // 128
#define GRID   (BATCH / ROWS_PER_BLOCK)          // 512  (single wave @ 4 CTA/SM)
#define NITERS 21                                 // 20 CCP steps + final apply
#define DIM4   (DIM / 4)                          // 256 float4 per row

__device__ __forceinline__ float dot8(const float4* __restrict__ x,
                                      const float4* __restrict__ w)
{
    float a = 0.f;
#pragma unroll
    for (int k = 0; k < 8; k++)
        a += x[k].x * w[k].x + x[k].y * w[k].y
           + x[k].z * w[k].z + x[k].w * w[k].w;
    return a;
}

__global__ void __launch_bounds__(THREADS, 4)
burden_kernel(const float* __restrict__ X,
              const float* __restrict__ w,
              const float* __restrict__ b,
              float* __restrict__ out)
{
    const int lane    = threadIdx.x & 31;
    const int warp    = threadIdx.x >> 5;
    const int rowBase = blockIdx.x * ROWS_PER_BLOCK + warp * ROWS_PER_WARP;

    // ---- w fragment in registers: lane owns float4 columns lane+32k ----
    const float4* w4p = reinterpret_cast<const float4*>(w);
    float4 w4[8];
#pragma unroll
    for (int k = 0; k < 8; k++) w4[k] = w4p[lane + 32 * k];

    // ---- ww = ||w||^2 (butterfly, all lanes) ----
    float wwp = dot8(w4, w4);
#pragma unroll
    for (int o = 16; o > 0; o >>= 1) wwp += __shfl_xor_sync(0xffffffffu, wwp, o);
    const float ww = wwp;
    const float b0 = b[0];

    const float4* base = reinterpret_cast<const float4*>(X)
                       + (size_t)rowBase * DIM4;

    // ---- pipelined row dots: A/B double buffer, loads always in flight ----
    float4 A[8], B[8];
#pragma unroll
    for (int k = 0; k < 8; k++) A[k] = __ldcs(base + lane + 32 * k);  // row 0

    float myS = 0.f;   // lane j ends up holding s0 for row rowBase + j
#pragma unroll 1
    for (int j = 0; j < ROWS_PER_WARP; j += 2) {
        // prefetch row j+1 into B (j+1 <= 31, always valid)
        const float4* pB = base + (size_t)(j + 1) * DIM4;
#pragma unroll
        for (int k = 0; k < 8; k++) B[k] = __ldcs(pB + lane + 32 * k);

        float a0 = dot8(A, w4);               // row j (A already resident)

        // prefetch row j+2 into A (predicated off on last iteration)
        if (j + 2 < ROWS_PER_WARP) {
            const float4* pA = base + (size_t)(j + 2) * DIM4;
#pragma unroll
            for (int k = 0; k < 8; k++) A[k] = __ldcs(pA + lane + 32 * k);
        }

        float a1 = dot8(B, w4);               // row j+1

        // merged 2-row reduction: 6 shuffles total
        a0 += __shfl_xor_sync(0xffffffffu, a0, 1);
        a1 += __shfl_xor_sync(0xffffffffu, a1, 1);
        float v = (lane & 1) ? a1 : a0;       // even lanes: a0 pairs, odd: a1
#pragma unroll
        for (int o = 2; o <= 16; o <<= 1)
            v += __shfl_xor_sync(0xffffffffu, v, o);
        // even lanes now hold sum(a0), odd lanes hold sum(a1)
        if ((lane & ~1) == j) myS = v;        // lane j <- s0(row j), lane j+1 <- s0(row j+1)
    }

    // ---- per-row scalar CCP recurrence, lane-parallel ----
    const float t0 = myS + b0;
    const float c  = 0.5f * ww;
    float s = t0;
#pragma unroll
    for (int it = 0; it < NITERS; it++) {
        float z   = s + 1.0f;                       // slope = 1
        float nab = 0.5f * z * rsqrtf(z * z + 1.0f);
        s = t0 + c * nab;
    }
    out[rowBase + lane] = s;   // coalesced
}

extern "C" void kernel_launch(void* const* d_in, const int* in_sizes, int n_in,
                              void* d_out, int out_size)
{
    const float* X = (const float*)d_in[0];
    const float* w = (const float*)d_in[1];
    const float* b = (const float*)d_in[2];
    float* out = (float*)d_out;
    (void)in_sizes; (void)n_in; (void)out_size;

    burden_kernel<<<GRID, THREADS>>>(X, w, b, out);
}